// round 5
// baseline (speedup 1.0000x reference)
#include <cuda_runtime.h>
#include <cuda_bf16.h>

#define N_MAX   100000
#define E_MAX   1600000
#define F_IN    128
#define HID     16
#define D_OUT   128

// Scratch
__device__ float   d_dinv[N_MAX];
__device__ int     d_deg [N_MAX];            // edge-only in-degree (no self loop)
__device__ int     d_row [N_MAX];            // CSR row start (exclusive scan of deg)
__device__ int     d_cur [N_MAX];            // fill cursor
__device__ int     d_csr [E_MAX];            // src ids grouped by dst
__device__ int2    d_edge2[E_MAX];           // converted & clamped (src, dst)
__device__ float4  d_g1  [N_MAX * HID / 4];  // (x@W1)*dinv
__device__ float4  d_t   [N_MAX * HID / 4];  // layer-1 output, pre-scaled by dinv
__device__ float4  d_agg2[N_MAX * HID / 4];  // layer-2 raw aggregate
__device__ int     d_idx64;                  // 1 if edge buffer is int64

// ---------------------------------------------------------------------------
// Zero deg + cursor
// ---------------------------------------------------------------------------
__global__ void k_init(int n) {
    int i = blockIdx.x * blockDim.x + threadIdx.x;
    if (i < n) { d_deg[i] = 0; d_cur[i] = 0; }
}

// ---------------------------------------------------------------------------
// Detect index width: if the first 1024 int64 words are all in [0, n) the
// buffer is genuine int64; int32 data read as int64 has huge high words.
// ---------------------------------------------------------------------------
__global__ void k_detect(const long long* __restrict__ ei, int n) {
    __shared__ int ok;
    if (threadIdx.x == 0) ok = 1;
    __syncthreads();
    long long v = ei[threadIdx.x];
    if (v < 0 || v >= (long long)n) ok = 0;   // benign race, all write 0
    __syncthreads();
    if (threadIdx.x == 0) d_idx64 = ok;
}

// ---------------------------------------------------------------------------
// Fused convert + degree histogram (int atomics)
// ---------------------------------------------------------------------------
__global__ void k_cvt_deg(const void* __restrict__ ei, int e, int n) {
    int i = blockIdx.x * blockDim.x + threadIdx.x;
    if (i >= e) return;
    long long sv, dv;
    if (d_idx64) {
        const long long* p = (const long long*)ei;
        sv = p[i]; dv = p[e + i];
    } else {
        const int* p = (const int*)ei;
        sv = p[i]; dv = p[e + i];
    }
    int2 pr;
    pr.x = (sv < 0) ? 0 : (sv >= n ? n - 1 : (int)sv);
    pr.y = (dv < 0) ? 0 : (dv >= n ? n - 1 : (int)dv);
    d_edge2[i] = pr;
    atomicAdd(&d_deg[pr.y], 1);
}

// ---------------------------------------------------------------------------
// Single-block exclusive scan of deg -> row starts; dinv = rsqrt(deg+1).
// 1024 threads x 128-element chunks covers N <= 131072.
// ---------------------------------------------------------------------------
__global__ void k_scan(int n) {
    __shared__ int sums[1024];
    const int CH = 128;
    int t = threadIdx.x;
    int base = t * CH;
    int s = 0;
    #pragma unroll 4
    for (int i = 0; i < CH; i++) {
        int idx = base + i;
        if (idx < n) s += d_deg[idx];
    }
    sums[t] = s;
    __syncthreads();
    // Hillis-Steele inclusive scan over 1024 partial sums
    for (int off = 1; off < 1024; off <<= 1) {
        int v = (t >= off) ? sums[t - off] : 0;
        __syncthreads();
        sums[t] += v;
        __syncthreads();
    }
    int run = (t == 0) ? 0 : sums[t - 1];
    for (int i = 0; i < CH; i++) {
        int idx = base + i;
        if (idx < n) {
            int dg = d_deg[idx];
            d_row[idx]  = run;
            run += dg;
            d_dinv[idx] = rsqrtf((float)dg + 1.0f);
        }
    }
}

// ---------------------------------------------------------------------------
// CSR fill: slot = row[dst] + cursor[dst]++ ; csr[slot] = src
// ---------------------------------------------------------------------------
__global__ void k_csr_fill(int e) {
    int i = blockIdx.x * blockDim.x + threadIdx.x;
    if (i >= e) return;
    int2 p = d_edge2[i];
    int pos = d_row[p.y] + atomicAdd(&d_cur[p.y], 1);
    d_csr[pos] = p.x;
}

// ---------------------------------------------------------------------------
// GEMM1: g1[i][k] = (x[i] @ W1[:,k]) * dinv[i]
// block = 256 threads, tile = 16 nodes (16 threads per node, one per hidden k)
// ---------------------------------------------------------------------------
__global__ void k_gemm1(const float* __restrict__ x,
                        const float* __restrict__ W1, int n) {
    __shared__ float W1s[F_IN * HID];   // 8 KB
    __shared__ float xs[16][F_IN];      // 8 KB
    for (int i = threadIdx.x; i < F_IN * HID; i += 256) W1s[i] = W1[i];

    int ln = threadIdx.x >> 4;
    int k  = threadIdx.x & 15;
    int ntiles = (n + 15) >> 4;
    float* g1 = reinterpret_cast<float*>(d_g1);

    for (int tile = blockIdx.x; tile < ntiles; tile += gridDim.x) {
        int base = tile << 4;
        __syncthreads();
        for (int i = threadIdx.x; i < 16 * F_IN; i += 256) {
            int r = i >> 7, c = i & 127;
            int node = base + r;
            xs[r][c] = (node < n) ? x[(size_t)node * F_IN + c] : 0.0f;
        }
        __syncthreads();
        int node = base + ln;
        if (node < n) {
            float acc = 0.0f;
            #pragma unroll
            for (int c = 0; c < F_IN; c++)
                acc += xs[ln][c] * W1s[c * HID + k];
            g1[node * HID + k] = acc * d_dinv[node];
        }
    }
}

// ---------------------------------------------------------------------------
// Gather layer 1 (+ fused mid epilogue):
//   agg = g1[node] + sum_{s in N(node)} g1[s]
//   t[node] = relu(agg*dinv + b1) * dinv
// 4 threads per node, one float4 slice each.
// ---------------------------------------------------------------------------
__global__ void k_gather1(const float* __restrict__ b1, int n) {
    int gid = blockIdx.x * blockDim.x + threadIdx.x;
    int node = gid >> 2;
    if (node >= n) return;
    int q = (gid & 3) << 2;

    const float4* g = d_g1;
    int vidx = node * 4 + (q >> 2);
    float4 acc = g[vidx];                       // self loop
    int start = d_row[node];
    int cnt   = d_deg[node];

    int j = 0;
    for (; j + 2 <= cnt; j += 2) {
        int s0 = __ldg(&d_csr[start + j]);
        int s1 = __ldg(&d_csr[start + j + 1]);
        float4 v0 = g[s0 * 4 + (q >> 2)];
        float4 v1 = g[s1 * 4 + (q >> 2)];
        acc.x += v0.x + v1.x; acc.y += v0.y + v1.y;
        acc.z += v0.z + v1.z; acc.w += v0.w + v1.w;
    }
    if (j < cnt) {
        int s0 = __ldg(&d_csr[start + j]);
        float4 v0 = g[s0 * 4 + (q >> 2)];
        acc.x += v0.x; acc.y += v0.y; acc.z += v0.z; acc.w += v0.w;
    }

    float dv = d_dinv[node];
    float4 bb = *reinterpret_cast<const float4*>(b1 + q);
    float4 r;
    r.x = fmaxf(acc.x * dv + bb.x, 0.0f) * dv;
    r.y = fmaxf(acc.y * dv + bb.y, 0.0f) * dv;
    r.z = fmaxf(acc.z * dv + bb.z, 0.0f) * dv;
    r.w = fmaxf(acc.w * dv + bb.w, 0.0f) * dv;
    d_t[vidx] = r;
}

// ---------------------------------------------------------------------------
// Gather layer 2: agg2[node] = t[node] + sum_{s in N(node)} t[s]
// ---------------------------------------------------------------------------
__global__ void k_gather2(int n) {
    int gid = blockIdx.x * blockDim.x + threadIdx.x;
    int node = gid >> 2;
    if (node >= n) return;
    int q4 = gid & 3;

    const float4* g = d_t;
    int vidx = node * 4 + q4;
    float4 acc = g[vidx];                       // self loop
    int start = d_row[node];
    int cnt   = d_deg[node];

    int j = 0;
    for (; j + 2 <= cnt; j += 2) {
        int s0 = __ldg(&d_csr[start + j]);
        int s1 = __ldg(&d_csr[start + j + 1]);
        float4 v0 = g[s0 * 4 + q4];
        float4 v1 = g[s1 * 4 + q4];
        acc.x += v0.x + v1.x; acc.y += v0.y + v1.y;
        acc.z += v0.z + v1.z; acc.w += v0.w + v1.w;
    }
    if (j < cnt) {
        int s0 = __ldg(&d_csr[start + j]);
        float4 v0 = g[s0 * 4 + q4];
        acc.x += v0.x; acc.y += v0.y; acc.z += v0.z; acc.w += v0.w;
    }
    d_agg2[vidx] = acc;
}

// ---------------------------------------------------------------------------
// GEMM2 + epilogue: out[i][j] = relu((agg2[i]*dinv[i]) @ W2[:,j] + b2[j])
// ---------------------------------------------------------------------------
__global__ void k_gemm2(const float* __restrict__ W2,
                        const float* __restrict__ b2,
                        float* __restrict__ out, int n) {
    __shared__ float W2s[HID * D_OUT];  // 8 KB
    __shared__ float ts[4][HID];
    for (int i = threadIdx.x; i < HID * D_OUT; i += 512) W2s[i] = W2[i];

    int ln = threadIdx.x >> 7;
    int j  = threadIdx.x & 127;
    float bj = b2[j];
    int ntiles = (n + 3) >> 2;
    const float* agg2 = reinterpret_cast<const float*>(d_agg2);

    for (int tile = blockIdx.x; tile < ntiles; tile += gridDim.x) {
        int base = tile << 2;
        __syncthreads();
        if (threadIdx.x < 64) {
            int r = threadIdx.x >> 4, c = threadIdx.x & 15;
            int node = base + r;
            ts[r][c] = (node < n) ? agg2[node * HID + c] * d_dinv[node] : 0.0f;
        }
        __syncthreads();
        int node = base + ln;
        if (node < n) {
            float acc = bj;
            #pragma unroll
            for (int c = 0; c < HID; c++)
                acc += ts[ln][c] * W2s[c * D_OUT + j];
            out[(size_t)node * D_OUT + j] = fmaxf(acc, 0.0f);
        }
    }
}

// ---------------------------------------------------------------------------
// Launch — inputs identified by SIZE, not position
// ---------------------------------------------------------------------------
extern "C" void kernel_launch(void* const* d_in, const int* in_sizes, int n_in,
                              void* d_out, int out_size) {
    int ix = 0;
    for (int i = 1; i < n_in; i++) if (in_sizes[i] > in_sizes[ix]) ix = i;
    int ie = -1;
    for (int i = 0; i < n_in; i++) {
        if (i == ix) continue;
        if (ie < 0 || in_sizes[i] > in_sizes[ie]) ie = i;
    }
    int ib1 = -1, ib2 = -1, iw1 = -1, iw2 = -1;
    for (int i = 0; i < n_in; i++) {
        if (i == ix || i == ie) continue;
        if (in_sizes[i] == 16)       ib1 = i;
        else if (in_sizes[i] == 128) ib2 = i;
        else if (iw1 < 0)            iw1 = i;
        else                         iw2 = i;
    }

    const float* x   = (const float*)d_in[ix];
    const void*  ei  = d_in[ie];
    const float* W1  = (const float*)d_in[iw1];
    const float* b1  = (const float*)d_in[ib1];
    const float* W2  = (const float*)d_in[iw2];
    const float* b2  = (const float*)d_in[ib2];
    float*       out = (float*)d_out;

    int N = in_sizes[ix] / F_IN;    // 100000
    int E = in_sizes[ie] / 2;       // 1600000

    k_init    <<<(N + 255) / 256, 256>>>(N);
    k_detect  <<<1, 1024>>>((const long long*)ei, N);
    k_cvt_deg <<<(E + 255) / 256, 256>>>(ei, E, N);
    k_scan    <<<1, 1024>>>(N);
    k_csr_fill<<<(E + 255) / 256, 256>>>(E);

    k_gemm1<<<1480, 256>>>(x, W1, N);

    int ggrid = (4 * N + 255) / 256;
    k_gather1<<<ggrid, 256>>>(b1, N);
    k_gather2<<<ggrid, 256>>>(N);

    k_gemm2<<<1480, 512>>>(W2, b2, out, N);
}

// round 6
// speedup vs baseline: 2.3932x; 2.3932x over previous
#include <cuda_runtime.h>
#include <cuda_bf16.h>

#define N_MAX   100000
#define E_MAX   1600000
#define F_IN    128
#define HID     16
#define D_OUT   128
#define SCAN_B  256
#define NB_MAX  ((N_MAX + SCAN_B - 1) / SCAN_B)   // 391

// Scratch
__device__ float   d_dinv[N_MAX];
__device__ int     d_deg [N_MAX];            // edge-only in-degree (no self loop)
__device__ int     d_row [N_MAX];            // CSR row start (exclusive scan of deg)
__device__ int     d_cur [N_MAX];            // fill cursor
__device__ int     d_csr [E_MAX];            // src ids grouped by dst
__device__ int2    d_edge2[E_MAX];           // converted & clamped (src, dst)
__device__ float4  d_g1  [N_MAX * HID / 4];  // (x@W1)*dinv
__device__ float4  d_t   [N_MAX * HID / 4];  // layer-1 output, pre-scaled by dinv
__device__ float4  d_agg2[N_MAX * HID / 4];  // layer-2 raw aggregate
__device__ int     d_bsum[NB_MAX + 1];       // per-block partial sums / offsets
__device__ int     d_idx64;                  // 1 if edge buffer is int64

// ---------------------------------------------------------------------------
// Zero deg + cursor
// ---------------------------------------------------------------------------
__global__ void k_init(int n) {
    int i = blockIdx.x * blockDim.x + threadIdx.x;
    if (i < n) { d_deg[i] = 0; d_cur[i] = 0; }
}

// ---------------------------------------------------------------------------
// Detect index width: int32 data read as int64 has huge high words.
// ---------------------------------------------------------------------------
__global__ void k_detect(const long long* __restrict__ ei, int n) {
    __shared__ int ok;
    if (threadIdx.x == 0) ok = 1;
    __syncthreads();
    long long v = ei[threadIdx.x];
    if (v < 0 || v >= (long long)n) ok = 0;   // benign race, all write 0
    __syncthreads();
    if (threadIdx.x == 0) d_idx64 = ok;
}

// ---------------------------------------------------------------------------
// Fused convert + degree histogram (int atomics)
// ---------------------------------------------------------------------------
__global__ void k_cvt_deg(const void* __restrict__ ei, int e, int n) {
    int i = blockIdx.x * blockDim.x + threadIdx.x;
    if (i >= e) return;
    long long sv, dv;
    if (d_idx64) {
        const long long* p = (const long long*)ei;
        sv = p[i]; dv = p[e + i];
    } else {
        const int* p = (const int*)ei;
        sv = p[i]; dv = p[e + i];
    }
    int2 pr;
    pr.x = (sv < 0) ? 0 : (sv >= n ? n - 1 : (int)sv);
    pr.y = (dv < 0) ? 0 : (dv >= n ? n - 1 : (int)dv);
    d_edge2[i] = pr;
    atomicAdd(&d_deg[pr.y], 1);
}

// ---------------------------------------------------------------------------
// 3-phase exclusive scan of deg -> d_row, plus dinv = rsqrt(deg+1)
// ---------------------------------------------------------------------------
// Phase A: per-block tile reduction (coalesced)
__global__ void k_scanA(int n) {
    __shared__ int sh[SCAN_B];
    int i = blockIdx.x * SCAN_B + threadIdx.x;
    sh[threadIdx.x] = (i < n) ? d_deg[i] : 0;
    __syncthreads();
    for (int off = SCAN_B / 2; off > 0; off >>= 1) {
        if (threadIdx.x < off) sh[threadIdx.x] += sh[threadIdx.x + off];
        __syncthreads();
    }
    if (threadIdx.x == 0) d_bsum[blockIdx.x] = sh[0];
}

// Phase B: single small block scans the block sums (nb <= 512)
__global__ void k_scanB(int nb) {
    __shared__ int sh[512];
    int t = threadIdx.x;
    sh[t] = (t < nb) ? d_bsum[t] : 0;
    __syncthreads();
    for (int off = 1; off < 512; off <<= 1) {
        int v = (t >= off) ? sh[t - off] : 0;
        __syncthreads();
        sh[t] += v;
        __syncthreads();
    }
    if (t < nb) d_bsum[t] = (t == 0) ? 0 : 0;   // placeholder, real write below
    // exclusive: shift right by one
    if (t < nb) d_bsum[t] = (t == 0) ? 0 : sh[t - 1];
}

// Phase C: in-block exclusive scan + block offset; also writes dinv
__global__ void k_scanC(int n) {
    __shared__ int sh[SCAN_B];
    int i = blockIdx.x * SCAN_B + threadIdx.x;
    int dg = (i < n) ? d_deg[i] : 0;
    sh[threadIdx.x] = dg;
    __syncthreads();
    // Hillis-Steele inclusive scan
    for (int off = 1; off < SCAN_B; off <<= 1) {
        int v = (threadIdx.x >= off) ? sh[threadIdx.x - off] : 0;
        __syncthreads();
        sh[threadIdx.x] += v;
        __syncthreads();
    }
    if (i < n) {
        int excl = sh[threadIdx.x] - dg;             // exclusive within block
        d_row[i]  = excl + d_bsum[blockIdx.x];
        d_dinv[i] = rsqrtf((float)dg + 1.0f);
    }
}

// ---------------------------------------------------------------------------
// CSR fill: slot = row[dst] + cursor[dst]++ ; csr[slot] = src
// ---------------------------------------------------------------------------
__global__ void k_csr_fill(int e) {
    int i = blockIdx.x * blockDim.x + threadIdx.x;
    if (i >= e) return;
    int2 p = d_edge2[i];
    int pos = d_row[p.y] + atomicAdd(&d_cur[p.y], 1);
    d_csr[pos] = p.x;
}

// ---------------------------------------------------------------------------
// GEMM1: g1[i][k] = (x[i] @ W1[:,k]) * dinv[i]
// ---------------------------------------------------------------------------
__global__ void k_gemm1(const float* __restrict__ x,
                        const float* __restrict__ W1, int n) {
    __shared__ float W1s[F_IN * HID];   // 8 KB
    __shared__ float xs[16][F_IN];      // 8 KB
    for (int i = threadIdx.x; i < F_IN * HID; i += 256) W1s[i] = W1[i];

    int ln = threadIdx.x >> 4;
    int k  = threadIdx.x & 15;
    int ntiles = (n + 15) >> 4;
    float* g1 = reinterpret_cast<float*>(d_g1);

    for (int tile = blockIdx.x; tile < ntiles; tile += gridDim.x) {
        int base = tile << 4;
        __syncthreads();
        for (int i = threadIdx.x; i < 16 * F_IN; i += 256) {
            int r = i >> 7, c = i & 127;
            int node = base + r;
            xs[r][c] = (node < n) ? x[(size_t)node * F_IN + c] : 0.0f;
        }
        __syncthreads();
        int node = base + ln;
        if (node < n) {
            float acc = 0.0f;
            #pragma unroll
            for (int c = 0; c < F_IN; c++)
                acc += xs[ln][c] * W1s[c * HID + k];
            g1[node * HID + k] = acc * d_dinv[node];
        }
    }
}

// ---------------------------------------------------------------------------
// Gather layer 1 (+ fused mid epilogue):
//   t[node] = relu((g1[node] + sum_{s in N(node)} g1[s]) * dinv + b1) * dinv
// 4 threads per node, one float4 slice each.
// ---------------------------------------------------------------------------
__global__ void k_gather1(const float* __restrict__ b1, int n) {
    int gid = blockIdx.x * blockDim.x + threadIdx.x;
    int node = gid >> 2;
    if (node >= n) return;
    int q4 = gid & 3;

    const float4* g = d_g1;
    int vidx = node * 4 + q4;
    float4 acc = g[vidx];                       // self loop
    int start = d_row[node];
    int cnt   = d_deg[node];

    int j = 0;
    for (; j + 2 <= cnt; j += 2) {
        int s0 = __ldg(&d_csr[start + j]);
        int s1 = __ldg(&d_csr[start + j + 1]);
        float4 v0 = g[s0 * 4 + q4];
        float4 v1 = g[s1 * 4 + q4];
        acc.x += v0.x + v1.x; acc.y += v0.y + v1.y;
        acc.z += v0.z + v1.z; acc.w += v0.w + v1.w;
    }
    if (j < cnt) {
        int s0 = __ldg(&d_csr[start + j]);
        float4 v0 = g[s0 * 4 + q4];
        acc.x += v0.x; acc.y += v0.y; acc.z += v0.z; acc.w += v0.w;
    }

    float dv = d_dinv[node];
    float4 bb = *reinterpret_cast<const float4*>(b1 + q4 * 4);
    float4 r;
    r.x = fmaxf(acc.x * dv + bb.x, 0.0f) * dv;
    r.y = fmaxf(acc.y * dv + bb.y, 0.0f) * dv;
    r.z = fmaxf(acc.z * dv + bb.z, 0.0f) * dv;
    r.w = fmaxf(acc.w * dv + bb.w, 0.0f) * dv;
    d_t[vidx] = r;
}

// ---------------------------------------------------------------------------
// Gather layer 2: agg2[node] = t[node] + sum_{s in N(node)} t[s]
// ---------------------------------------------------------------------------
__global__ void k_gather2(int n) {
    int gid = blockIdx.x * blockDim.x + threadIdx.x;
    int node = gid >> 2;
    if (node >= n) return;
    int q4 = gid & 3;

    const float4* g = d_t;
    int vidx = node * 4 + q4;
    float4 acc = g[vidx];                       // self loop
    int start = d_row[node];
    int cnt   = d_deg[node];

    int j = 0;
    for (; j + 2 <= cnt; j += 2) {
        int s0 = __ldg(&d_csr[start + j]);
        int s1 = __ldg(&d_csr[start + j + 1]);
        float4 v0 = g[s0 * 4 + q4];
        float4 v1 = g[s1 * 4 + q4];
        acc.x += v0.x + v1.x; acc.y += v0.y + v1.y;
        acc.z += v0.z + v1.z; acc.w += v0.w + v1.w;
    }
    if (j < cnt) {
        int s0 = __ldg(&d_csr[start + j]);
        float4 v0 = g[s0 * 4 + q4];
        acc.x += v0.x; acc.y += v0.y; acc.z += v0.z; acc.w += v0.w;
    }
    d_agg2[vidx] = acc;
}

// ---------------------------------------------------------------------------
// GEMM2 + epilogue: out[i][j] = relu((agg2[i]*dinv[i]) @ W2[:,j] + b2[j])
// ---------------------------------------------------------------------------
__global__ void k_gemm2(const float* __restrict__ W2,
                        const float* __restrict__ b2,
                        float* __restrict__ out, int n) {
    __shared__ float W2s[HID * D_OUT];  // 8 KB
    __shared__ float ts[4][HID];
    for (int i = threadIdx.x; i < HID * D_OUT; i += 512) W2s[i] = W2[i];

    int ln = threadIdx.x >> 7;
    int j  = threadIdx.x & 127;
    float bj = b2[j];
    int ntiles = (n + 3) >> 2;
    const float* agg2 = reinterpret_cast<const float*>(d_agg2);

    for (int tile = blockIdx.x; tile < ntiles; tile += gridDim.x) {
        int base = tile << 2;
        __syncthreads();
        if (threadIdx.x < 64) {
            int r = threadIdx.x >> 4, c = threadIdx.x & 15;
            int node = base + r;
            ts[r][c] = (node < n) ? agg2[node * HID + c] * d_dinv[node] : 0.0f;
        }
        __syncthreads();
        int node = base + ln;
        if (node < n) {
            float acc = bj;
            #pragma unroll
            for (int c = 0; c < HID; c++)
                acc += ts[ln][c] * W2s[c * D_OUT + j];
            out[(size_t)node * D_OUT + j] = fmaxf(acc, 0.0f);
        }
    }
}

// ---------------------------------------------------------------------------
// Launch — inputs identified by SIZE, not position
// ---------------------------------------------------------------------------
extern "C" void kernel_launch(void* const* d_in, const int* in_sizes, int n_in,
                              void* d_out, int out_size) {
    int ix = 0;
    for (int i = 1; i < n_in; i++) if (in_sizes[i] > in_sizes[ix]) ix = i;
    int ie = -1;
    for (int i = 0; i < n_in; i++) {
        if (i == ix) continue;
        if (ie < 0 || in_sizes[i] > in_sizes[ie]) ie = i;
    }
    int ib1 = -1, ib2 = -1, iw1 = -1, iw2 = -1;
    for (int i = 0; i < n_in; i++) {
        if (i == ix || i == ie) continue;
        if (in_sizes[i] == 16)       ib1 = i;
        else if (in_sizes[i] == 128) ib2 = i;
        else if (iw1 < 0)            iw1 = i;
        else                         iw2 = i;
    }

    const float* x   = (const float*)d_in[ix];
    const void*  ei  = d_in[ie];
    const float* W1  = (const float*)d_in[iw1];
    const float* b1  = (const float*)d_in[ib1];
    const float* W2  = (const float*)d_in[iw2];
    const float* b2  = (const float*)d_in[ib2];
    float*       out = (float*)d_out;

    int N = in_sizes[ix] / F_IN;    // 100000
    int E = in_sizes[ie] / 2;       // 1600000
    int NB = (N + SCAN_B - 1) / SCAN_B;   // 391

    k_init    <<<(N + 255) / 256, 256>>>(N);
    k_detect  <<<1, 1024>>>((const long long*)ei, N);
    k_cvt_deg <<<(E + 255) / 256, 256>>>(ei, E, N);
    k_scanA   <<<NB, SCAN_B>>>(N);
    k_scanB   <<<1, 512>>>(NB);
    k_scanC   <<<NB, SCAN_B>>>(N);
    k_csr_fill<<<(E + 255) / 256, 256>>>(E);

    k_gemm1<<<1480, 256>>>(x, W1, N);

    int ggrid = (4 * N + 255) / 256;
    k_gather1<<<ggrid, 256>>>(b1, N);
    k_gather2<<<ggrid, 256>>>(N);

    k_gemm2<<<1480, 512>>>(W2, b2, out, N);
}